// round 12
// baseline (speedup 1.0000x reference)
#include <cuda_runtime.h>
#include <cuda_fp16.h>
#include <cstdint>

// Problem constants
#define BATCH 32
#define SEQ   576
#define CH    768
#define NH    12
#define HD    64
#define MROWS (BATCH * SEQ)      // 18432
#define QKVC  (3 * CH)           // 2304
#define GRID24 24
#define BS4   4

// ---------------------------------------------------------------------------
// Scratch (__device__ globals; no allocations allowed)
// ---------------------------------------------------------------------------
__device__ float  g_q  [(size_t)MROWS * CH];     // Q fp32 (gemm1 out, sec 0)
__device__ __half g_kh [(size_t)MROWS * CH];     // K hi fp16 (sec 1)
__device__ __half g_kl [(size_t)MROWS * CH];     // K lo fp16 (sec 1)
__device__ __half g_vh [(size_t)MROWS * CH];     // V fp16 (sec 2)
__device__ __half g_xh [(size_t)MROWS * CH];     // x fp16
__device__ __half g_wqh[(size_t)QKVC * CH];      // qkv_w fp16
__device__ __half g_wph[(size_t)CH * CH];        // proj_w fp16
__device__ __half g_ath[(size_t)MROWS * CH];     // attention out fp16

__device__ __forceinline__ int block_idx_of(int p) {
    int i = p / GRID24;
    int j = p - i * GRID24;
    return (i >> 2) * (GRID24 / BS4) + (j >> 2);
}

// ---------------------------------------------------------------------------
// helpers
// ---------------------------------------------------------------------------
__device__ __forceinline__ void cp_async16(void* smem, const void* gmem) {
    uint32_t s = (uint32_t)__cvta_generic_to_shared(smem);
    asm volatile("cp.async.cg.shared.global [%0], [%1], 16;\n" :: "r"(s), "l"(gmem));
}
__device__ __forceinline__ void cp_async16_u(uint32_t smem, const void* gmem) {
    asm volatile("cp.async.cg.shared.global [%0], [%1], 16;\n" :: "r"(smem), "l"(gmem));
}
__device__ __forceinline__ void cp_commit() {
    asm volatile("cp.async.commit_group;\n");
}
template<int N>
__device__ __forceinline__ void cp_wait() {
    asm volatile("cp.async.wait_group %0;\n" :: "n"(N));
}
__device__ __forceinline__ uint32_t smem_u32(const void* p) {
    uint32_t a;
    asm("{ .reg .u64 t; cvta.to.shared.u64 t, %1; cvt.u32.u64 %0, t; }" : "=r"(a) : "l"(p));
    return a;
}
#define LDMATRIX_X4(r0, r1, r2, r3, addr)                                       \
    asm volatile("ldmatrix.sync.aligned.m8n8.x4.shared.b16 {%0,%1,%2,%3}, [%4];" \
                 : "=r"(r0), "=r"(r1), "=r"(r2), "=r"(r3) : "r"(addr))
#define LDMATRIX_X4_T(r0, r1, r2, r3, addr)                                     \
    asm volatile("ldmatrix.sync.aligned.m8n8.x4.trans.shared.b16 {%0,%1,%2,%3}, [%4];" \
                 : "=r"(r0), "=r"(r1), "=r"(r2), "=r"(r3) : "r"(addr))

#define MMA_F16(acc, a0,a1,a2,a3, b0,b1)                                        \
    asm volatile(                                                               \
        "mma.sync.aligned.m16n8k16.row.col.f32.f16.f16.f32 "                    \
        "{%0,%1,%2,%3}, {%4,%5,%6,%7}, {%8,%9}, {%0,%1,%2,%3};\n"               \
        : "+f"(acc[0]), "+f"(acc[1]), "+f"(acc[2]), "+f"(acc[3])                \
        : "r"(a0), "r"(a1), "r"(a2), "r"(a3), "r"(b0), "r"(b1))

// Fast exp on FMA pipe
__device__ __forceinline__ float fexp(float x) {
    x = fmaxf(x, -87.0f);
    float t = x * 1.44269504f;
    int   ei = __float2int_rn(t);
    float fn = (float)ei;
    float r  = fmaf(fn, -0.69314718f, x);
    float p  = 8.3333337e-3f;
    p = fmaf(p, r, 4.1666668e-2f);
    p = fmaf(p, r, 0.16666667f);
    p = fmaf(p, r, 0.5f);
    p = fmaf(p, r, 1.0f);
    p = fmaf(p, r, 1.0f);
    return p * __int_as_float((ei + 127) << 23);
}

__device__ __forceinline__ uint32_t pack_h2(__half2 h) { return *(uint32_t*)&h; }

// ---------------------------------------------------------------------------
// Pre-pass: fp32 row-major -> fp16 row-major
// ---------------------------------------------------------------------------
__global__ void pack_half(const float* __restrict__ src, __half* __restrict__ dst,
                          int total4)
{
    int idx = blockIdx.x * blockDim.x + threadIdx.x;
    if (idx >= total4) return;
    float4 f = *(const float4*)(src + (size_t)idx * 4);
    ((__half2*)dst)[idx * 2]     = __floats2half2_rn(f.x, f.y);
    ((__half2*)dst)[idx * 2 + 1] = __floats2half2_rn(f.z, f.w);
}

// ---------------------------------------------------------------------------
// FP16 tensor-core GEMM (NT): 3-stage cp.async, one barrier/iter, hoisted
// addressing. 128x128x32 CTA tile, 8 warps, m16n8k16.
// ---------------------------------------------------------------------------
#define BKH 32
#define LDH 40
#define STG_H (128 * LDH)                  // halves per matrix per stage (5120)
#define GEMM_SMEM (6 * STG_H * 2)          // 61440 bytes

template<int ROUTE>
__global__ __launch_bounds__(256)
void gemm_fp16(const __half* __restrict__ A, const __half* __restrict__ Bm,
               const float* __restrict__ bias, float* __restrict__ Cm,
               __half* __restrict__ KH, __half* __restrict__ KL,
               __half* __restrict__ VH, int ncols, int Kd)
{
    extern __shared__ __half smh[];
    __half* As = smh;                      // [3][STG_H]
    __half* Bs = smh + 3 * STG_H;          // [3][STG_H]

    const int tid  = threadIdx.x;
    const int wid  = tid >> 5;
    const int lane = tid & 31;
    const int g    = lane >> 2;
    const int t4   = lane & 3;
    const int wm   = (wid & 3) * 32;
    const int wn   = (wid >> 2) * 64;
    const int bx = blockIdx.x, by = blockIdx.y;

    const __half* Ag = A  + (size_t)(by * 128) * Kd;
    const __half* Bg = Bm + (size_t)(bx * 128) * Kd;

    float acc[2][8][4];
#pragma unroll
    for (int mt = 0; mt < 2; mt++)
#pragma unroll
        for (int nt = 0; nt < 8; nt++)
#pragma unroll
            for (int r = 0; r < 4; r++) acc[mt][nt][r] = 0.f;

    // --- hoisted load addressing: each thread owns 2 chunks per matrix ---
    const int r0 = tid >> 2,            c0 = (tid & 3) << 3;
    const int r1 = (tid + 256) >> 2,    c1 = ((tid + 256) & 3) << 3;
    const __half* pA0 = Ag + (size_t)r0 * Kd + c0;
    const __half* pA1 = Ag + (size_t)r1 * Kd + c1;
    const __half* pB0 = Bg + (size_t)r0 * Kd + c0;
    const __half* pB1 = Bg + (size_t)r1 * Kd + c1;
    const uint32_t sA0 = smem_u32(As) + (r0 * LDH + c0) * 2;
    const uint32_t sA1 = smem_u32(As) + (r1 * LDH + c1) * 2;
    const uint32_t sB0 = smem_u32(Bs) + (r0 * LDH + c0) * 2;
    const uint32_t sB1 = smem_u32(Bs) + (r1 * LDH + c1) * 2;

    // --- hoisted ldmatrix addressing (per warp lane) ---
    const int a_row = (lane & 7) + ((lane >> 3) & 1) * 8;
    const int a_ch  = ((lane >> 4) & 1) * 8;
    const int b_row = (lane & 7) + ((lane >> 4) & 1) * 8;
    const int b_ch  = ((lane >> 3) & 1) * 8;
    uint32_t aB[2], bB[4];
#pragma unroll
    for (int mt = 0; mt < 2; mt++)
        aB[mt] = smem_u32(As) + ((wm + mt * 16 + a_row) * LDH + a_ch) * 2;
#pragma unroll
    for (int np = 0; np < 4; np++)
        bB[np] = smem_u32(Bs) + ((wn + np * 16 + b_row) * LDH + b_ch) * 2;

    const int nk = Kd / BKH;   // 24

    auto issue = [&](int kt, int s) {
        const int off = kt * BKH;               // halves
        const uint32_t so = (uint32_t)(s * (STG_H * 2));  // bytes
        cp_async16_u(sA0 + so, pA0 + off);
        cp_async16_u(sA1 + so, pA1 + off);
        cp_async16_u(sB0 + so, pB0 + off);
        cp_async16_u(sB1 + so, pB1 + off);
        cp_commit();
    };

    issue(0, 0);
    issue(1, 1);

    for (int kt = 0; kt < nk; kt++) {
        const int s = kt % 3;
        if (kt < nk - 1) cp_wait<1>(); else cp_wait<0>();
        __syncthreads();
        if (kt + 2 < nk) issue(kt + 2, (kt + 2) % 3);

        const uint32_t so = (uint32_t)(s * (STG_H * 2));
#pragma unroll
        for (int kk = 0; kk < 2; kk++) {
            const uint32_t ko = so + kk * 32;   // 16 halves = 32 bytes
            uint32_t af[2][4];
#pragma unroll
            for (int mt = 0; mt < 2; mt++)
                LDMATRIX_X4(af[mt][0], af[mt][1], af[mt][2], af[mt][3], aB[mt] + ko);
#pragma unroll
            for (int np = 0; np < 4; np++) {
                uint32_t b0, b1, b2, b3;
                LDMATRIX_X4(b0, b1, b2, b3, bB[np] + ko);
#pragma unroll
                for (int mt = 0; mt < 2; mt++) {
                    MMA_F16(acc[mt][np * 2],     af[mt][0], af[mt][1], af[mt][2], af[mt][3], b0, b1);
                    MMA_F16(acc[mt][np * 2 + 1], af[mt][0], af[mt][1], af[mt][2], af[mt][3], b2, b3);
                }
            }
        }
        // no trailing barrier: next iteration's barrier protects stage reuse
    }

    if (ROUTE == 0) {
#pragma unroll
        for (int mt = 0; mt < 2; mt++) {
            const int row = by * 128 + wm + mt * 16 + g;
#pragma unroll
            for (int nt = 0; nt < 8; nt++) {
                const int col = bx * 128 + wn + nt * 8 + (t4 << 1);
                float bx0 = bias[col], bx1 = bias[col + 1];
                float2 v0, v1;
                v0.x = acc[mt][nt][0] + bx0; v0.y = acc[mt][nt][1] + bx1;
                v1.x = acc[mt][nt][2] + bx0; v1.y = acc[mt][nt][3] + bx1;
                *(float2*)(Cm + (size_t)row * ncols + col)       = v0;
                *(float2*)(Cm + (size_t)(row + 8) * ncols + col) = v1;
            }
        }
    } else {
        const int sec = bx / 6;
        const int cb  = bx * 128 - sec * 768;
#pragma unroll
        for (int mt = 0; mt < 2; mt++) {
            const int row = by * 128 + wm + mt * 16 + g;
#pragma unroll
            for (int nt = 0; nt < 8; nt++) {
                const int colr = cb + wn + nt * 8 + (t4 << 1);
                const int colg = sec * 768 + colr;
                float bx0 = bias[colg], bx1 = bias[colg + 1];
                float r0a = acc[mt][nt][0] + bx0, r1a = acc[mt][nt][1] + bx1;
                float r2a = acc[mt][nt][2] + bx0, r3a = acc[mt][nt][3] + bx1;
                if (sec == 0) {
                    float2 v0; v0.x = r0a; v0.y = r1a;
                    float2 v1; v1.x = r2a; v1.y = r3a;
                    *(float2*)(Cm + (size_t)row * CH + colr)       = v0;
                    *(float2*)(Cm + (size_t)(row + 8) * CH + colr) = v1;
                } else if (sec == 1) {
                    __half2 h0 = __floats2half2_rn(r0a, r1a);
                    __half2 h1 = __floats2half2_rn(r2a, r3a);
                    float2 f0 = __half22float2(h0), f1 = __half22float2(h1);
                    __half2 l0 = __floats2half2_rn(r0a - f0.x, r1a - f0.y);
                    __half2 l1 = __floats2half2_rn(r2a - f1.x, r3a - f1.y);
                    *(__half2*)(KH + (size_t)row * CH + colr)       = h0;
                    *(__half2*)(KH + (size_t)(row + 8) * CH + colr) = h1;
                    *(__half2*)(KL + (size_t)row * CH + colr)       = l0;
                    *(__half2*)(KL + (size_t)(row + 8) * CH + colr) = l1;
                } else {
                    *(__half2*)(VH + (size_t)row * CH + colr)       = __floats2half2_rn(r0a, r1a);
                    *(__half2*)(VH + (size_t)(row + 8) * CH + colr) = __floats2half2_rn(r2a, r3a);
                }
            }
        }
    }
}

// ---------------------------------------------------------------------------
// FP16 block-causal flash attention: 192 q-rows per CTA (12 warps), K/V tiles
// shared across 3x the MMA work. Double-buffered stages, visibility fast path.
// ---------------------------------------------------------------------------
#define LDK 72
#define KV_TILE_H (64 * LDK)                            // halves per array
#define ATTN_SMEM (2 * 3 * KV_TILE_H * 2 + SEQ * 4 + 4 * 32)
#define QROWS 192

__global__ __launch_bounds__(384)
void attn_fp16(const float* __restrict__ Qf,
               const __half* __restrict__ Kh, const __half* __restrict__ Kl,
               const __half* __restrict__ Vh, __half* __restrict__ atth)
{
    extern __shared__ char smraw[];
    __half* sStage = (__half*)smraw;                    // [2][3*KV_TILE_H]: Kh,Kl,V
    int* kbi  = (int*)(sStage + 2 * 3 * KV_TILE_H);     // [SEQ]
    int* kmin = kbi + SEQ;                              // [9]
    int* kmax = kmin + 9;                               // [9]
    int* act  = kmax + 9;                               // [9]
    int* meta = act + 9;                                // [0]=nact, [1]=maxbq, [2]=minbq

    const int b = blockIdx.z, h = blockIdx.y, qt = blockIdx.x;   // qt in 0..2
    const int tid = threadIdx.x, wid = tid >> 5, lane = tid & 31;
    const int g = lane >> 2, t4 = lane & 3;
    const int wm = wid * 16;                             // 0..176

    for (int p = tid; p < SEQ; p += 384) kbi[p] = block_idx_of(p);
    __syncthreads();
    if (tid < 9) {
        int mn = 1 << 30, mx = -1;
        for (int j = 0; j < 64; j++) {
            int v = kbi[tid * 64 + j];
            mn = min(mn, v); mx = max(mx, v);
        }
        kmin[tid] = mn; kmax[tid] = mx;
    }
    __syncthreads();
    if (tid == 0) {
        int mxq = -1, mnq = 1 << 30;
        for (int j = 0; j < QROWS; j++) {
            int v = kbi[qt * QROWS + j];
            mxq = max(mxq, v); mnq = min(mnq, v);
        }
        int n = 0;
        for (int kt = 0; kt < 9; kt++)
            if (kmin[kt] <= mxq) act[n++] = kt;
        meta[0] = n; meta[1] = mxq; meta[2] = mnq;
    }
    __syncthreads();

    const int nact  = meta[0];
    const int minbq = meta[2];
    const int qr0 = qt * QROWS + wm + g;
    const int bq0 = kbi[qr0];
    const int bq1 = kbi[qr0 + 8];

    // Q fragments, pre-scaled by 1/8, fp16 hi/lo split
    uint32_t qh[4][4], ql[4][4];
    {
        const float* Qp0 = Qf + (size_t)(b * SEQ + qr0) * CH + h * HD;
        const float* Qp1 = Qp0 + (size_t)8 * CH;
#pragma unroll
        for (int kc = 0; kc < 4; kc++) {
            float2 x00 = *(const float2*)(Qp0 + kc * 16 + 2 * t4);
            float2 x10 = *(const float2*)(Qp1 + kc * 16 + 2 * t4);
            float2 x01 = *(const float2*)(Qp0 + kc * 16 + 8 + 2 * t4);
            float2 x11 = *(const float2*)(Qp1 + kc * 16 + 8 + 2 * t4);
            x00.x *= 0.125f; x00.y *= 0.125f; x10.x *= 0.125f; x10.y *= 0.125f;
            x01.x *= 0.125f; x01.y *= 0.125f; x11.x *= 0.125f; x11.y *= 0.125f;
            __half2 h0 = __floats2half2_rn(x00.x, x00.y);
            __half2 h1 = __floats2half2_rn(x10.x, x10.y);
            __half2 h2 = __floats2half2_rn(x01.x, x01.y);
            __half2 h3 = __floats2half2_rn(x11.x, x11.y);
            float2 f0 = __half22float2(h0), f1 = __half22float2(h1);
            float2 f2 = __half22float2(h2), f3 = __half22float2(h3);
            qh[kc][0] = pack_h2(h0); ql[kc][0] = pack_h2(__floats2half2_rn(x00.x - f0.x, x00.y - f0.y));
            qh[kc][1] = pack_h2(h1); ql[kc][1] = pack_h2(__floats2half2_rn(x10.x - f1.x, x10.y - f1.y));
            qh[kc][2] = pack_h2(h2); ql[kc][2] = pack_h2(__floats2half2_rn(x01.x - f2.x, x01.y - f2.y));
            qh[kc][3] = pack_h2(h3); ql[kc][3] = pack_h2(__floats2half2_rn(x11.x - f3.x, x11.y - f3.y));
        }
    }

    float m0 = -1e30f, m1 = -1e30f, l0 = 0.f, l1 = 0.f;
    float o[8][4];
#pragma unroll
    for (int nt = 0; nt < 8; nt++)
#pragma unroll
        for (int r = 0; r < 4; r++) o[nt][r] = 0.f;

    const int b_row = (lane & 7) + ((lane >> 4) & 1) * 8;
    const int b_ch  = ((lane >> 3) & 1) * 8;
    const int t_row = (lane & 7) + ((lane >> 3) & 1) * 8;
    const int t_ch  = ((lane >> 4) & 1) * 8;

    // 1536 16B-chunks per stage (3 arrays x 512), 384 threads -> 4 each
    auto issue_tile = [&](int kt, int s) {
        const size_t rowbase = (size_t)(b * SEQ + kt * 64) * CH + h * HD;
        const __half* gK = Kh + rowbase;
        const __half* gL = Kl + rowbase;
        const __half* gV = Vh + rowbase;
        __half* dst = sStage + s * (3 * KV_TILE_H);
#pragma unroll
        for (int i = 0; i < 4; i++) {
            int u   = tid + i * 384;
            int arr = u >> 9;               // 0..2
            int w   = u & 511;
            int r   = w >> 3, c = (w & 7) << 3;
            const __half* gb = (arr == 0) ? gK : ((arr == 1) ? gL : gV);
            cp_async16(&dst[arr * KV_TILE_H + r * LDK + c], gb + (size_t)r * CH + c);
        }
        cp_commit();
    };

    issue_tile(act[0], 0);
    if (nact > 1) issue_tile(act[1], 1);

    for (int ia = 0; ia < nact; ia++) {
        const int kt = act[ia];
        const int s  = ia & 1;
        const bool fullvis = (kmax[kt] <= minbq);

        if (ia + 1 < nact) cp_wait<1>(); else cp_wait<0>();
        __syncthreads();

        const __half* cKh = sStage + s * (3 * KV_TILE_H);
        const __half* cKl = cKh + KV_TILE_H;
        const __half* cV  = cKh + 2 * KV_TILE_H;

        // S = Q K^T (3-term fp16 split)
        float sacc[8][4];
#pragma unroll
        for (int nt = 0; nt < 8; nt++)
#pragma unroll
            for (int r = 0; r < 4; r++) sacc[nt][r] = 0.f;

#pragma unroll
        for (int kc = 0; kc < 4; kc++) {
            const int k0 = kc * 16;
#pragma unroll
            for (int np = 0; np < 4; np++) {
                uint32_t h0, h1, h2, h3, lo0, lo1, lo2, lo3;
                uint32_t ah = smem_u32(&cKh[(np * 16 + b_row) * LDK + k0 + b_ch]);
                uint32_t al = smem_u32(&cKl[(np * 16 + b_row) * LDK + k0 + b_ch]);
                LDMATRIX_X4(h0, h1, h2, h3, ah);
                LDMATRIX_X4(lo0, lo1, lo2, lo3, al);
                MMA_F16(sacc[np * 2],     qh[kc][0], qh[kc][1], qh[kc][2], qh[kc][3], h0, h1);
                MMA_F16(sacc[np * 2 + 1], qh[kc][0], qh[kc][1], qh[kc][2], qh[kc][3], h2, h3);
                MMA_F16(sacc[np * 2],     qh[kc][0], qh[kc][1], qh[kc][2], qh[kc][3], lo0, lo1);
                MMA_F16(sacc[np * 2 + 1], qh[kc][0], qh[kc][1], qh[kc][2], qh[kc][3], lo2, lo3);
                MMA_F16(sacc[np * 2],     ql[kc][0], ql[kc][1], ql[kc][2], ql[kc][3], h0, h1);
                MMA_F16(sacc[np * 2 + 1], ql[kc][0], ql[kc][1], ql[kc][2], ql[kc][3], h2, h3);
            }
        }

        if (!fullvis) {
            const int c0 = kt * 64;
#pragma unroll
            for (int nt = 0; nt < 8; nt++) {
                int k0b = kbi[c0 + nt * 8 + 2 * t4];
                int k1b = kbi[c0 + nt * 8 + 2 * t4 + 1];
                if (k0b > bq0) sacc[nt][0] = -1e30f;
                if (k1b > bq0) sacc[nt][1] = -1e30f;
                if (k0b > bq1) sacc[nt][2] = -1e30f;
                if (k1b > bq1) sacc[nt][3] = -1e30f;
            }
        }

        // Row max
        float mx0 = -1e30f, mx1 = -1e30f;
#pragma unroll
        for (int nt = 0; nt < 8; nt++) {
            mx0 = fmaxf(mx0, fmaxf(sacc[nt][0], sacc[nt][1]));
            mx1 = fmaxf(mx1, fmaxf(sacc[nt][2], sacc[nt][3]));
        }
        mx0 = fmaxf(mx0, __shfl_xor_sync(0xffffffffu, mx0, 1));
        mx0 = fmaxf(mx0, __shfl_xor_sync(0xffffffffu, mx0, 2));
        mx1 = fmaxf(mx1, __shfl_xor_sync(0xffffffffu, mx1, 1));
        mx1 = fmaxf(mx1, __shfl_xor_sync(0xffffffffu, mx1, 2));

        float nm0 = fmaxf(m0, mx0), nm1 = fmaxf(m1, mx1);
        float cr0 = fexp(m0 - nm0), cr1 = fexp(m1 - nm1);
        m0 = nm0; m1 = nm1;
        l0 *= cr0; l1 *= cr1;
#pragma unroll
        for (int nt = 0; nt < 8; nt++) {
            o[nt][0] *= cr0; o[nt][1] *= cr0;
            o[nt][2] *= cr1; o[nt][3] *= cr1;
        }

        // p = exp(s - m) -> fp16 fragments (register-direct A operand for PV)
        uint32_t pa[4][4];
        float s0 = 0.f, s1 = 0.f;
#pragma unroll
        for (int nt = 0; nt < 8; nt++) {
            float p0, p1, p2, p3;
            if (fullvis) {
                p0 = fexp(sacc[nt][0] - nm0);
                p1 = fexp(sacc[nt][1] - nm0);
                p2 = fexp(sacc[nt][2] - nm1);
                p3 = fexp(sacc[nt][3] - nm1);
            } else {
                p0 = (sacc[nt][0] > -1e29f) ? fexp(sacc[nt][0] - nm0) : 0.f;
                p1 = (sacc[nt][1] > -1e29f) ? fexp(sacc[nt][1] - nm0) : 0.f;
                p2 = (sacc[nt][2] > -1e29f) ? fexp(sacc[nt][2] - nm1) : 0.f;
                p3 = (sacc[nt][3] > -1e29f) ? fexp(sacc[nt][3] - nm1) : 0.f;
            }
            __half2 h01 = __floats2half2_rn(p0, p1);
            __half2 h23 = __floats2half2_rn(p2, p3);
            float2 f01 = __half22float2(h01), f23 = __half22float2(h23);
            s0 += f01.x + f01.y; s1 += f23.x + f23.y;
            int kc2 = nt >> 1, hi = (nt & 1) << 1;
            pa[kc2][hi]     = pack_h2(h01);
            pa[kc2][hi + 1] = pack_h2(h23);
        }
        s0 += __shfl_xor_sync(0xffffffffu, s0, 1);
        s0 += __shfl_xor_sync(0xffffffffu, s0, 2);
        s1 += __shfl_xor_sync(0xffffffffu, s1, 1);
        s1 += __shfl_xor_sync(0xffffffffu, s1, 2);
        l0 += s0; l1 += s1;

        // O += P @ V
#pragma unroll
        for (int kc2 = 0; kc2 < 4; kc2++) {
#pragma unroll
            for (int dp = 0; dp < 4; dp++) {
                uint32_t v0, v1, v2, v3;
                uint32_t addr = smem_u32(&cV[(kc2 * 16 + t_row) * LDK + dp * 16 + t_ch]);
                LDMATRIX_X4_T(v0, v1, v2, v3, addr);
                MMA_F16(o[dp * 2],     pa[kc2][0], pa[kc2][1], pa[kc2][2], pa[kc2][3], v0, v1);
                MMA_F16(o[dp * 2 + 1], pa[kc2][0], pa[kc2][1], pa[kc2][2], pa[kc2][3], v2, v3);
            }
        }

        __syncthreads();                        // all warps done with stage s
        if (ia + 2 < nact) issue_tile(act[ia + 2], s);
    }

    // Epilogue: normalize + store fp16 (feeds GEMM2)
    const float inv0 = 1.f / l0, inv1 = 1.f / l1;
    __half* Or0 = atth + (size_t)(b * SEQ + qr0) * CH + h * HD;
    __half* Or1 = Or0 + (size_t)8 * CH;
#pragma unroll
    for (int nt = 0; nt < 8; nt++) {
        *(__half2*)(Or0 + nt * 8 + 2 * t4) = __floats2half2_rn(o[nt][0] * inv0, o[nt][1] * inv0);
        *(__half2*)(Or1 + nt * 8 + 2 * t4) = __floats2half2_rn(o[nt][2] * inv1, o[nt][3] * inv1);
    }
}

// ---------------------------------------------------------------------------
// Launch
// ---------------------------------------------------------------------------
extern "C" void kernel_launch(void* const* d_in, const int* in_sizes, int n_in,
                              void* d_out, int out_size)
{
    const float* x      = (const float*)d_in[0];
    const float* qkv_w  = (const float*)d_in[1];
    const float* qkv_b  = (const float*)d_in[2];
    const float* proj_w = (const float*)d_in[3];
    const float* proj_b = (const float*)d_in[4];
    float* out = (float*)d_out;

    float* qbuf;
    __half *khb, *klb, *vhb, *xh, *wqh, *wph, *ath;
    cudaGetSymbolAddress((void**)&qbuf, g_q);
    cudaGetSymbolAddress((void**)&khb, g_kh);
    cudaGetSymbolAddress((void**)&klb, g_kl);
    cudaGetSymbolAddress((void**)&vhb, g_vh);
    cudaGetSymbolAddress((void**)&xh,  g_xh);
    cudaGetSymbolAddress((void**)&wqh, g_wqh);
    cudaGetSymbolAddress((void**)&wph, g_wph);
    cudaGetSymbolAddress((void**)&ath, g_ath);

    cudaFuncSetAttribute(gemm_fp16<0>, cudaFuncAttributeMaxDynamicSharedMemorySize, GEMM_SMEM);
    cudaFuncSetAttribute(gemm_fp16<1>, cudaFuncAttributeMaxDynamicSharedMemorySize, GEMM_SMEM);
    cudaFuncSetAttribute(attn_fp16, cudaFuncAttributeMaxDynamicSharedMemorySize, ATTN_SMEM);

    // Pre-pass: fp32 -> fp16
    pack_half<<<(MROWS * CH / 4 + 255) / 256, 256>>>(x, xh, MROWS * CH / 4);
    pack_half<<<(QKVC  * CH / 4 + 255) / 256, 256>>>(qkv_w, wqh, QKVC * CH / 4);
    pack_half<<<(CH    * CH / 4 + 255) / 256, 256>>>(proj_w, wph, CH * CH / 4);

    // 1) qkv = x @ qkv_w^T + qkv_b, routed: Q fp32 / K hi+lo / V fp16
    dim3 g1(QKVC / 128, MROWS / 128);    // (18, 144)
    gemm_fp16<1><<<g1, 256, GEMM_SMEM>>>(xh, wqh, qkv_b, qbuf, khb, klb, vhb, CH, CH);

    // 2) fp16 block-causal flash attention (192 q-rows per CTA)
    dim3 g2(SEQ / QROWS, NH, BATCH);     // (3, 12, 32)
    attn_fp16<<<g2, 384, ATTN_SMEM>>>(qbuf, khb, klb, vhb, ath);

    // 3) out = att @ proj_w^T + proj_b
    dim3 g3(CH / 128, MROWS / 128);      // (6, 144)
    gemm_fp16<0><<<g3, 256, GEMM_SMEM>>>(ath, wph, proj_b, out, nullptr, nullptr, nullptr, CH, CH);
}

// round 15
// speedup vs baseline: 1.0737x; 1.0737x over previous
#include <cuda_runtime.h>
#include <cuda_fp16.h>
#include <cstdint>

// Problem constants
#define BATCH 32
#define SEQ   576
#define CH    768
#define NH    12
#define HD    64
#define MROWS (BATCH * SEQ)      // 18432
#define QKVC  (3 * CH)           // 2304
#define GRID24 24
#define BS4   4

// ---------------------------------------------------------------------------
// Scratch (__device__ globals; no allocations allowed)
// ---------------------------------------------------------------------------
__device__ float  g_q  [(size_t)MROWS * CH];     // Q fp32 (gemm1 out, sec 0)
__device__ __half g_kh [(size_t)MROWS * CH];     // K hi fp16 (sec 1)
__device__ __half g_kl [(size_t)MROWS * CH];     // K lo fp16 (sec 1)
__device__ __half g_vh [(size_t)MROWS * CH];     // V fp16 (sec 2)
__device__ __half g_xh [(size_t)MROWS * CH];     // x fp16
__device__ __half g_wqh[(size_t)QKVC * CH];      // qkv_w fp16
__device__ __half g_wph[(size_t)CH * CH];        // proj_w fp16
__device__ __half g_ath[(size_t)MROWS * CH];     // attention out fp16

__device__ __forceinline__ int block_idx_of(int p) {
    int i = p / GRID24;
    int j = p - i * GRID24;
    return (i >> 2) * (GRID24 / BS4) + (j >> 2);
}

// ---------------------------------------------------------------------------
// helpers
// ---------------------------------------------------------------------------
__device__ __forceinline__ void cp_async16(void* smem, const void* gmem) {
    uint32_t s = (uint32_t)__cvta_generic_to_shared(smem);
    asm volatile("cp.async.cg.shared.global [%0], [%1], 16;\n" :: "r"(s), "l"(gmem));
}
__device__ __forceinline__ void cp_async16_u(uint32_t smem, const void* gmem) {
    asm volatile("cp.async.cg.shared.global [%0], [%1], 16;\n" :: "r"(smem), "l"(gmem));
}
__device__ __forceinline__ void cp_commit() {
    asm volatile("cp.async.commit_group;\n");
}
template<int N>
__device__ __forceinline__ void cp_wait() {
    asm volatile("cp.async.wait_group %0;\n" :: "n"(N));
}
__device__ __forceinline__ uint32_t smem_u32(const void* p) {
    uint32_t a;
    asm("{ .reg .u64 t; cvta.to.shared.u64 t, %1; cvt.u32.u64 %0, t; }" : "=r"(a) : "l"(p));
    return a;
}
#define LDMATRIX_X4(r0, r1, r2, r3, addr)                                       \
    asm volatile("ldmatrix.sync.aligned.m8n8.x4.shared.b16 {%0,%1,%2,%3}, [%4];" \
                 : "=r"(r0), "=r"(r1), "=r"(r2), "=r"(r3) : "r"(addr))
#define LDMATRIX_X4_T(r0, r1, r2, r3, addr)                                     \
    asm volatile("ldmatrix.sync.aligned.m8n8.x4.trans.shared.b16 {%0,%1,%2,%3}, [%4];" \
                 : "=r"(r0), "=r"(r1), "=r"(r2), "=r"(r3) : "r"(addr))

#define MMA_F16(acc, a0,a1,a2,a3, b0,b1)                                        \
    asm volatile(                                                               \
        "mma.sync.aligned.m16n8k16.row.col.f32.f16.f16.f32 "                    \
        "{%0,%1,%2,%3}, {%4,%5,%6,%7}, {%8,%9}, {%0,%1,%2,%3};\n"               \
        : "+f"(acc[0]), "+f"(acc[1]), "+f"(acc[2]), "+f"(acc[3])                \
        : "r"(a0), "r"(a1), "r"(a2), "r"(a3), "r"(b0), "r"(b1))

// Fast exp on FMA pipe
__device__ __forceinline__ float fexp(float x) {
    x = fmaxf(x, -87.0f);
    float t = x * 1.44269504f;
    int   ei = __float2int_rn(t);
    float fn = (float)ei;
    float r  = fmaf(fn, -0.69314718f, x);
    float p  = 8.3333337e-3f;
    p = fmaf(p, r, 4.1666668e-2f);
    p = fmaf(p, r, 0.16666667f);
    p = fmaf(p, r, 0.5f);
    p = fmaf(p, r, 1.0f);
    p = fmaf(p, r, 1.0f);
    return p * __int_as_float((ei + 127) << 23);
}

__device__ __forceinline__ uint32_t pack_h2(__half2 h) { return *(uint32_t*)&h; }

// ---------------------------------------------------------------------------
// Pre-pass: fp32 row-major -> fp16 row-major
// ---------------------------------------------------------------------------
__global__ void pack_half(const float* __restrict__ src, __half* __restrict__ dst,
                          int total4)
{
    int idx = blockIdx.x * blockDim.x + threadIdx.x;
    if (idx >= total4) return;
    float4 f = *(const float4*)(src + (size_t)idx * 4);
    ((__half2*)dst)[idx * 2]     = __floats2half2_rn(f.x, f.y);
    ((__half2*)dst)[idx * 2 + 1] = __floats2half2_rn(f.z, f.w);
}

// ---------------------------------------------------------------------------
// FP16 tensor-core GEMM (NT): 3-stage cp.async, one barrier/iter, hoisted
// addressing (R12 version — at the mma.sync dispatch floor).
// ---------------------------------------------------------------------------
#define BKH 32
#define LDH 40
#define STG_H (128 * LDH)                  // halves per matrix per stage (5120)
#define GEMM_SMEM (6 * STG_H * 2)          // 61440 bytes

template<int ROUTE>
__global__ __launch_bounds__(256)
void gemm_fp16(const __half* __restrict__ A, const __half* __restrict__ Bm,
               const float* __restrict__ bias, float* __restrict__ Cm,
               __half* __restrict__ KH, __half* __restrict__ KL,
               __half* __restrict__ VH, int ncols, int Kd)
{
    extern __shared__ __half smh[];
    __half* As = smh;                      // [3][STG_H]
    __half* Bs = smh + 3 * STG_H;          // [3][STG_H]

    const int tid  = threadIdx.x;
    const int wid  = tid >> 5;
    const int lane = tid & 31;
    const int g    = lane >> 2;
    const int t4   = lane & 3;
    const int wm   = (wid & 3) * 32;
    const int wn   = (wid >> 2) * 64;
    const int bx = blockIdx.x, by = blockIdx.y;

    const __half* Ag = A  + (size_t)(by * 128) * Kd;
    const __half* Bg = Bm + (size_t)(bx * 128) * Kd;

    float acc[2][8][4];
#pragma unroll
    for (int mt = 0; mt < 2; mt++)
#pragma unroll
        for (int nt = 0; nt < 8; nt++)
#pragma unroll
            for (int r = 0; r < 4; r++) acc[mt][nt][r] = 0.f;

    const int r0 = tid >> 2,            c0 = (tid & 3) << 3;
    const int r1 = (tid + 256) >> 2,    c1 = ((tid + 256) & 3) << 3;
    const __half* pA0 = Ag + (size_t)r0 * Kd + c0;
    const __half* pA1 = Ag + (size_t)r1 * Kd + c1;
    const __half* pB0 = Bg + (size_t)r0 * Kd + c0;
    const __half* pB1 = Bg + (size_t)r1 * Kd + c1;
    const uint32_t sA0 = smem_u32(As) + (r0 * LDH + c0) * 2;
    const uint32_t sA1 = smem_u32(As) + (r1 * LDH + c1) * 2;
    const uint32_t sB0 = smem_u32(Bs) + (r0 * LDH + c0) * 2;
    const uint32_t sB1 = smem_u32(Bs) + (r1 * LDH + c1) * 2;

    const int a_row = (lane & 7) + ((lane >> 3) & 1) * 8;
    const int a_ch  = ((lane >> 4) & 1) * 8;
    const int b_row = (lane & 7) + ((lane >> 4) & 1) * 8;
    const int b_ch  = ((lane >> 3) & 1) * 8;
    uint32_t aB[2], bB[4];
#pragma unroll
    for (int mt = 0; mt < 2; mt++)
        aB[mt] = smem_u32(As) + ((wm + mt * 16 + a_row) * LDH + a_ch) * 2;
#pragma unroll
    for (int np = 0; np < 4; np++)
        bB[np] = smem_u32(Bs) + ((wn + np * 16 + b_row) * LDH + b_ch) * 2;

    const int nk = Kd / BKH;   // 24

    auto issue = [&](int kt, int s) {
        const int off = kt * BKH;
        const uint32_t so = (uint32_t)(s * (STG_H * 2));
        cp_async16_u(sA0 + so, pA0 + off);
        cp_async16_u(sA1 + so, pA1 + off);
        cp_async16_u(sB0 + so, pB0 + off);
        cp_async16_u(sB1 + so, pB1 + off);
        cp_commit();
    };

    issue(0, 0);
    issue(1, 1);

    for (int kt = 0; kt < nk; kt++) {
        const int s = kt % 3;
        if (kt < nk - 1) cp_wait<1>(); else cp_wait<0>();
        __syncthreads();
        if (kt + 2 < nk) issue(kt + 2, (kt + 2) % 3);

        const uint32_t so = (uint32_t)(s * (STG_H * 2));
#pragma unroll
        for (int kk = 0; kk < 2; kk++) {
            const uint32_t ko = so + kk * 32;
            uint32_t af[2][4];
#pragma unroll
            for (int mt = 0; mt < 2; mt++)
                LDMATRIX_X4(af[mt][0], af[mt][1], af[mt][2], af[mt][3], aB[mt] + ko);
#pragma unroll
            for (int np = 0; np < 4; np++) {
                uint32_t b0, b1, b2, b3;
                LDMATRIX_X4(b0, b1, b2, b3, bB[np] + ko);
#pragma unroll
                for (int mt = 0; mt < 2; mt++) {
                    MMA_F16(acc[mt][np * 2],     af[mt][0], af[mt][1], af[mt][2], af[mt][3], b0, b1);
                    MMA_F16(acc[mt][np * 2 + 1], af[mt][0], af[mt][1], af[mt][2], af[mt][3], b2, b3);
                }
            }
        }
    }

    if (ROUTE == 0) {
#pragma unroll
        for (int mt = 0; mt < 2; mt++) {
            const int row = by * 128 + wm + mt * 16 + g;
#pragma unroll
            for (int nt = 0; nt < 8; nt++) {
                const int col = bx * 128 + wn + nt * 8 + (t4 << 1);
                float bx0 = bias[col], bx1 = bias[col + 1];
                float2 v0, v1;
                v0.x = acc[mt][nt][0] + bx0; v0.y = acc[mt][nt][1] + bx1;
                v1.x = acc[mt][nt][2] + bx0; v1.y = acc[mt][nt][3] + bx1;
                *(float2*)(Cm + (size_t)row * ncols + col)       = v0;
                *(float2*)(Cm + (size_t)(row + 8) * ncols + col) = v1;
            }
        }
    } else {
        const int sec = bx / 6;
        const int cb  = bx * 128 - sec * 768;
#pragma unroll
        for (int mt = 0; mt < 2; mt++) {
            const int row = by * 128 + wm + mt * 16 + g;
#pragma unroll
            for (int nt = 0; nt < 8; nt++) {
                const int colr = cb + wn + nt * 8 + (t4 << 1);
                const int colg = sec * 768 + colr;
                float bx0 = bias[colg], bx1 = bias[colg + 1];
                float r0a = acc[mt][nt][0] + bx0, r1a = acc[mt][nt][1] + bx1;
                float r2a = acc[mt][nt][2] + bx0, r3a = acc[mt][nt][3] + bx1;
                if (sec == 0) {
                    float2 v0; v0.x = r0a; v0.y = r1a;
                    float2 v1; v1.x = r2a; v1.y = r3a;
                    *(float2*)(Cm + (size_t)row * CH + colr)       = v0;
                    *(float2*)(Cm + (size_t)(row + 8) * CH + colr) = v1;
                } else if (sec == 1) {
                    __half2 h0 = __floats2half2_rn(r0a, r1a);
                    __half2 h1 = __floats2half2_rn(r2a, r3a);
                    float2 f0 = __half22float2(h0), f1 = __half22float2(h1);
                    __half2 l0 = __floats2half2_rn(r0a - f0.x, r1a - f0.y);
                    __half2 l1 = __floats2half2_rn(r2a - f1.x, r3a - f1.y);
                    *(__half2*)(KH + (size_t)row * CH + colr)       = h0;
                    *(__half2*)(KH + (size_t)(row + 8) * CH + colr) = h1;
                    *(__half2*)(KL + (size_t)row * CH + colr)       = l0;
                    *(__half2*)(KL + (size_t)(row + 8) * CH + colr) = l1;
                } else {
                    *(__half2*)(VH + (size_t)row * CH + colr)       = __floats2half2_rn(r0a, r1a);
                    *(__half2*)(VH + (size_t)(row + 8) * CH + colr) = __floats2half2_rn(r2a, r3a);
                }
            }
        }
    }
}

// ---------------------------------------------------------------------------
// FP16 block-causal flash attention — R7-proven version: 64 q-rows / 128
// threads per CTA (fine-grained tile skipping), double-buffered K/V,
// visibility fast path.
// ---------------------------------------------------------------------------
#define LDK 72
#define KV_TILE_H (64 * LDK)                    // halves per array per stage
#define ATTN_SMEM (2 * 3 * KV_TILE_H * 2 + SEQ * 4 + 4 * 32)

__global__ __launch_bounds__(128)
void attn_fp16(const float* __restrict__ Qf,
               const __half* __restrict__ Kh, const __half* __restrict__ Kl,
               const __half* __restrict__ Vh, __half* __restrict__ atth)
{
    extern __shared__ char smraw[];
    __half* sKh = (__half*)smraw;                        // [2][KV_TILE_H]
    __half* sKl = sKh + 2 * KV_TILE_H;
    __half* sV  = sKl + 2 * KV_TILE_H;
    int* kbi   = (int*)(sV + 2 * KV_TILE_H);             // [SEQ]
    int* kmin  = kbi + SEQ;                              // [9]
    int* kmax  = kmin + 9;                               // [9]
    int* act   = kmax + 9;                               // [9]
    int* meta  = act + 9;                                // [0]=nact, [2]=minbq

    const int b = blockIdx.z, h = blockIdx.y, qt = blockIdx.x;
    const int tid = threadIdx.x, wid = tid >> 5, lane = tid & 31;
    const int g = lane >> 2, t4 = lane & 3;
    const int wm = wid * 16;

    for (int p = tid; p < SEQ; p += 128) kbi[p] = block_idx_of(p);
    __syncthreads();
    if (tid < 9) {
        int mn = 1 << 30, mx = -1;
        for (int j = 0; j < 64; j++) {
            int v = kbi[tid * 64 + j];
            mn = min(mn, v); mx = max(mx, v);
        }
        kmin[tid] = mn; kmax[tid] = mx;
    }
    __syncthreads();
    if (tid == 0) {
        int mxq = kmax[qt], mnq = kmin[qt];
        int n = 0;
        for (int kt = 0; kt < 9; kt++)
            if (kmin[kt] <= mxq) act[n++] = kt;
        meta[0] = n; meta[2] = mnq;
    }
    __syncthreads();

    const int nact  = meta[0];
    const int minbq = meta[2];
    const int qr0 = qt * 64 + wm + g;
    const int bq0 = kbi[qr0];
    const int bq1 = kbi[qr0 + 8];

    // Q fragments, pre-scaled by 1/8, fp16 hi/lo split
    uint32_t qh[4][4], ql[4][4];
    {
        const float* Qp0 = Qf + (size_t)(b * SEQ + qr0) * CH + h * HD;
        const float* Qp1 = Qp0 + (size_t)8 * CH;
#pragma unroll
        for (int kc = 0; kc < 4; kc++) {
            float2 x00 = *(const float2*)(Qp0 + kc * 16 + 2 * t4);
            float2 x10 = *(const float2*)(Qp1 + kc * 16 + 2 * t4);
            float2 x01 = *(const float2*)(Qp0 + kc * 16 + 8 + 2 * t4);
            float2 x11 = *(const float2*)(Qp1 + kc * 16 + 8 + 2 * t4);
            x00.x *= 0.125f; x00.y *= 0.125f; x10.x *= 0.125f; x10.y *= 0.125f;
            x01.x *= 0.125f; x01.y *= 0.125f; x11.x *= 0.125f; x11.y *= 0.125f;
            __half2 h0 = __floats2half2_rn(x00.x, x00.y);
            __half2 h1 = __floats2half2_rn(x10.x, x10.y);
            __half2 h2 = __floats2half2_rn(x01.x, x01.y);
            __half2 h3 = __floats2half2_rn(x11.x, x11.y);
            float2 f0 = __half22float2(h0), f1 = __half22float2(h1);
            float2 f2 = __half22float2(h2), f3 = __half22float2(h3);
            qh[kc][0] = pack_h2(h0); ql[kc][0] = pack_h2(__floats2half2_rn(x00.x - f0.x, x00.y - f0.y));
            qh[kc][1] = pack_h2(h1); ql[kc][1] = pack_h2(__floats2half2_rn(x10.x - f1.x, x10.y - f1.y));
            qh[kc][2] = pack_h2(h2); ql[kc][2] = pack_h2(__floats2half2_rn(x01.x - f2.x, x01.y - f2.y));
            qh[kc][3] = pack_h2(h3); ql[kc][3] = pack_h2(__floats2half2_rn(x11.x - f3.x, x11.y - f3.y));
        }
    }

    float m0 = -1e30f, m1 = -1e30f, l0 = 0.f, l1 = 0.f;
    float o[8][4];
#pragma unroll
    for (int nt = 0; nt < 8; nt++)
#pragma unroll
        for (int r = 0; r < 4; r++) o[nt][r] = 0.f;

    const int b_row = (lane & 7) + ((lane >> 4) & 1) * 8;
    const int b_ch  = ((lane >> 3) & 1) * 8;
    const int t_row = (lane & 7) + ((lane >> 3) & 1) * 8;
    const int t_ch  = ((lane >> 4) & 1) * 8;

    auto issue_tile = [&](int kt, int s) {
        const __half* Kgh = Kh + (size_t)(b * SEQ + kt * 64) * CH + h * HD;
        const __half* Kgl = Kl + (size_t)(b * SEQ + kt * 64) * CH + h * HD;
        const __half* Vg  = Vh + (size_t)(b * SEQ + kt * 64) * CH + h * HD;
        __half* dKh = sKh + s * KV_TILE_H;
        __half* dKl = sKl + s * KV_TILE_H;
        __half* dV  = sV  + s * KV_TILE_H;
#pragma unroll
        for (int i = 0; i < 4; i++) {
            int u = tid + i * 128;
            int r = u >> 3, c = (u & 7) << 3;
            cp_async16(&dKh[r * LDK + c], Kgh + (size_t)r * CH + c);
            cp_async16(&dKl[r * LDK + c], Kgl + (size_t)r * CH + c);
            cp_async16(&dV [r * LDK + c], Vg  + (size_t)r * CH + c);
        }
        cp_commit();
    };

    issue_tile(act[0], 0);
    if (nact > 1) issue_tile(act[1], 1);

    for (int ia = 0; ia < nact; ia++) {
        const int kt = act[ia];
        const int s  = ia & 1;
        const bool fullvis = (kmax[kt] <= minbq);

        if (ia + 1 < nact) cp_wait<1>(); else cp_wait<0>();
        __syncthreads();

        const __half* cKh = sKh + s * KV_TILE_H;
        const __half* cKl = sKl + s * KV_TILE_H;
        const __half* cV  = sV  + s * KV_TILE_H;

        // S = Q K^T (3-term fp16 split)
        float sacc[8][4];
#pragma unroll
        for (int nt = 0; nt < 8; nt++)
#pragma unroll
            for (int r = 0; r < 4; r++) sacc[nt][r] = 0.f;

#pragma unroll
        for (int kc = 0; kc < 4; kc++) {
            const int k0 = kc * 16;
#pragma unroll
            for (int np = 0; np < 4; np++) {
                uint32_t h0, h1, h2, h3, lo0, lo1, lo2, lo3;
                uint32_t ah = smem_u32(&cKh[(np * 16 + b_row) * LDK + k0 + b_ch]);
                uint32_t al = smem_u32(&cKl[(np * 16 + b_row) * LDK + k0 + b_ch]);
                LDMATRIX_X4(h0, h1, h2, h3, ah);
                LDMATRIX_X4(lo0, lo1, lo2, lo3, al);
                MMA_F16(sacc[np * 2],     qh[kc][0], qh[kc][1], qh[kc][2], qh[kc][3], h0, h1);
                MMA_F16(sacc[np * 2 + 1], qh[kc][0], qh[kc][1], qh[kc][2], qh[kc][3], h2, h3);
                MMA_F16(sacc[np * 2],     qh[kc][0], qh[kc][1], qh[kc][2], qh[kc][3], lo0, lo1);
                MMA_F16(sacc[np * 2 + 1], qh[kc][0], qh[kc][1], qh[kc][2], qh[kc][3], lo2, lo3);
                MMA_F16(sacc[np * 2],     ql[kc][0], ql[kc][1], ql[kc][2], ql[kc][3], h0, h1);
                MMA_F16(sacc[np * 2 + 1], ql[kc][0], ql[kc][1], ql[kc][2], ql[kc][3], h2, h3);
            }
        }

        if (!fullvis) {
            const int c0 = kt * 64;
#pragma unroll
            for (int nt = 0; nt < 8; nt++) {
                int k0b = kbi[c0 + nt * 8 + 2 * t4];
                int k1b = kbi[c0 + nt * 8 + 2 * t4 + 1];
                if (k0b > bq0) sacc[nt][0] = -1e30f;
                if (k1b > bq0) sacc[nt][1] = -1e30f;
                if (k0b > bq1) sacc[nt][2] = -1e30f;
                if (k1b > bq1) sacc[nt][3] = -1e30f;
            }
        }

        // Row max
        float mx0 = -1e30f, mx1 = -1e30f;
#pragma unroll
        for (int nt = 0; nt < 8; nt++) {
            mx0 = fmaxf(mx0, fmaxf(sacc[nt][0], sacc[nt][1]));
            mx1 = fmaxf(mx1, fmaxf(sacc[nt][2], sacc[nt][3]));
        }
        mx0 = fmaxf(mx0, __shfl_xor_sync(0xffffffffu, mx0, 1));
        mx0 = fmaxf(mx0, __shfl_xor_sync(0xffffffffu, mx0, 2));
        mx1 = fmaxf(mx1, __shfl_xor_sync(0xffffffffu, mx1, 1));
        mx1 = fmaxf(mx1, __shfl_xor_sync(0xffffffffu, mx1, 2));

        float nm0 = fmaxf(m0, mx0), nm1 = fmaxf(m1, mx1);
        float cr0 = fexp(m0 - nm0), cr1 = fexp(m1 - nm1);
        m0 = nm0; m1 = nm1;
        l0 *= cr0; l1 *= cr1;
#pragma unroll
        for (int nt = 0; nt < 8; nt++) {
            o[nt][0] *= cr0; o[nt][1] *= cr0;
            o[nt][2] *= cr1; o[nt][3] *= cr1;
        }

        // p = exp(s - m) -> fp16 fragments (register-direct A operand for PV)
        uint32_t pa[4][4];
        float s0 = 0.f, s1 = 0.f;
#pragma unroll
        for (int nt = 0; nt < 8; nt++) {
            float p0, p1, p2, p3;
            if (fullvis) {
                p0 = fexp(sacc[nt][0] - nm0);
                p1 = fexp(sacc[nt][1] - nm0);
                p2 = fexp(sacc[nt][2] - nm1);
                p3 = fexp(sacc[nt][3] - nm1);
            } else {
                p0 = (sacc[nt][0] > -1e29f) ? fexp(sacc[nt][0] - nm0) : 0.f;
                p1 = (sacc[nt][1] > -1e29f) ? fexp(sacc[nt][1] - nm0) : 0.f;
                p2 = (sacc[nt][2] > -1e29f) ? fexp(sacc[nt][2] - nm1) : 0.f;
                p3 = (sacc[nt][3] > -1e29f) ? fexp(sacc[nt][3] - nm1) : 0.f;
            }
            __half2 h01 = __floats2half2_rn(p0, p1);
            __half2 h23 = __floats2half2_rn(p2, p3);
            float2 f01 = __half22float2(h01), f23 = __half22float2(h23);
            s0 += f01.x + f01.y; s1 += f23.x + f23.y;
            int kc2 = nt >> 1, hi = (nt & 1) << 1;
            pa[kc2][hi]     = pack_h2(h01);
            pa[kc2][hi + 1] = pack_h2(h23);
        }
        s0 += __shfl_xor_sync(0xffffffffu, s0, 1);
        s0 += __shfl_xor_sync(0xffffffffu, s0, 2);
        s1 += __shfl_xor_sync(0xffffffffu, s1, 1);
        s1 += __shfl_xor_sync(0xffffffffu, s1, 2);
        l0 += s0; l1 += s1;

        // O += P @ V (V via ldmatrix.trans)
#pragma unroll
        for (int kc2 = 0; kc2 < 4; kc2++) {
#pragma unroll
            for (int dp = 0; dp < 4; dp++) {
                uint32_t v0, v1, v2, v3;
                uint32_t addr = smem_u32(&cV[(kc2 * 16 + t_row) * LDK + dp * 16 + t_ch]);
                LDMATRIX_X4_T(v0, v1, v2, v3, addr);
                MMA_F16(o[dp * 2],     pa[kc2][0], pa[kc2][1], pa[kc2][2], pa[kc2][3], v0, v1);
                MMA_F16(o[dp * 2 + 1], pa[kc2][0], pa[kc2][1], pa[kc2][2], pa[kc2][3], v2, v3);
            }
        }

        __syncthreads();                        // all warps done with stage s
        if (ia + 2 < nact) issue_tile(act[ia + 2], s);
    }

    // Epilogue: normalize + store fp16 (feeds GEMM2)
    const float inv0 = 1.f / l0, inv1 = 1.f / l1;
    __half* Or0 = atth + (size_t)(b * SEQ + qr0) * CH + h * HD;
    __half* Or1 = Or0 + (size_t)8 * CH;
#pragma unroll
    for (int nt = 0; nt < 8; nt++) {
        *(__half2*)(Or0 + nt * 8 + 2 * t4) = __floats2half2_rn(o[nt][0] * inv0, o[nt][1] * inv0);
        *(__half2*)(Or1 + nt * 8 + 2 * t4) = __floats2half2_rn(o[nt][2] * inv1, o[nt][3] * inv1);
    }
}

// ---------------------------------------------------------------------------
// Launch
// ---------------------------------------------------------------------------
extern "C" void kernel_launch(void* const* d_in, const int* in_sizes, int n_in,
                              void* d_out, int out_size)
{
    const float* x      = (const float*)d_in[0];
    const float* qkv_w  = (const float*)d_in[1];
    const float* qkv_b  = (const float*)d_in[2];
    const float* proj_w = (const float*)d_in[3];
    const float* proj_b = (const float*)d_in[4];
    float* out = (float*)d_out;

    float* qbuf;
    __half *khb, *klb, *vhb, *xh, *wqh, *wph, *ath;
    cudaGetSymbolAddress((void**)&qbuf, g_q);
    cudaGetSymbolAddress((void**)&khb, g_kh);
    cudaGetSymbolAddress((void**)&klb, g_kl);
    cudaGetSymbolAddress((void**)&vhb, g_vh);
    cudaGetSymbolAddress((void**)&xh,  g_xh);
    cudaGetSymbolAddress((void**)&wqh, g_wqh);
    cudaGetSymbolAddress((void**)&wph, g_wph);
    cudaGetSymbolAddress((void**)&ath, g_ath);

    cudaFuncSetAttribute(gemm_fp16<0>, cudaFuncAttributeMaxDynamicSharedMemorySize, GEMM_SMEM);
    cudaFuncSetAttribute(gemm_fp16<1>, cudaFuncAttributeMaxDynamicSharedMemorySize, GEMM_SMEM);
    cudaFuncSetAttribute(attn_fp16, cudaFuncAttributeMaxDynamicSharedMemorySize, ATTN_SMEM);

    // Pre-pass: fp32 -> fp16
    pack_half<<<(MROWS * CH / 4 + 255) / 256, 256>>>(x, xh, MROWS * CH / 4);
    pack_half<<<(QKVC  * CH / 4 + 255) / 256, 256>>>(qkv_w, wqh, QKVC * CH / 4);
    pack_half<<<(CH    * CH / 4 + 255) / 256, 256>>>(proj_w, wph, CH * CH / 4);

    // 1) qkv = x @ qkv_w^T + qkv_b, routed: Q fp32 / K hi+lo / V fp16
    dim3 g1(QKVC / 128, MROWS / 128);    // (18, 144)
    gemm_fp16<1><<<g1, 256, GEMM_SMEM>>>(xh, wqh, qkv_b, qbuf, khb, klb, vhb, CH, CH);

    // 2) fp16 block-causal flash attention (64 q-rows per CTA — fine skipping)
    dim3 g2(SEQ / 64, NH, BATCH);        // (9, 12, 32)
    attn_fp16<<<g2, 128, ATTN_SMEM>>>(qbuf, khb, klb, vhb, ath);

    // 3) out = att @ proj_w^T + proj_b
    dim3 g3(CH / 128, MROWS / 128);      // (6, 144)
    gemm_fp16<0><<<g3, 256, GEMM_SMEM>>>(ath, wph, proj_b, out, nullptr, nullptr, nullptr, CH, CH);
}